// round 14
// baseline (speedup 1.0000x reference)
#include <cuda_runtime.h>
#include <cstdint>

#define TH 1.0f
#define EPS_BN 1e-5f

// scratch (no allocations allowed -> device globals)
__device__ float g_dm[256 * 256];
__device__ int   g_rowok[256];
__device__ int   g_done = 0;   // reset by last tg==0 block each run (replay-safe)

__device__ __forceinline__ uint32_t smem_u32(const void* p) {
    uint32_t a;
    asm("{ .reg .u64 t; cvta.to.shared.u64 t, %1; cvt.u32.u64 %0, t; }"
        : "=r"(a) : "l"(p));
    return a;
}
__device__ __forceinline__ void s2g(void* gdst, uint32_t ssrc, uint32_t bytes) {
    asm volatile("cp.async.bulk.global.shared::cta.bulk_group [%0], [%1], %2;"
                 :: "l"(gdst), "r"(ssrc), "r"(bytes) : "memory");
}

// ---------------------------------------------------------------------------
// Single fused kernel, 2304 blocks x 256 threads:
//  b in [0,256)    : dist blocks. chunk = b&31 -> rows n0=chunk*8 .. +8,
//    tg = b>>5 -> t-copies t = tg*16 .. +16. Thread m computes the 8-row MLP
//    slab into smem (8KB), then ONE thread issues 16 non-blocking 8KB
//    cp.async.bulk S2G stores into dist_mat_full (TMA path, bypasses L1).
//    tg==0 blocks also write g_dm rows + rowok and join a 32-count
//    done-counter; the last computes group_indices in-kernel
//    (fast path all-zeros; exact lax.scan replica fallback).
//  b in [256,2304) : float4 slab copy v_rel -> v_grouped on the LSU path
//    (stop_gradient(v - v_soft) + v_soft == v exactly).
// The two data paths (L1/LSU for the 67MB copy, TMA for the 33.5MB dist
// stores) run concurrently.
// ---------------------------------------------------------------------------
__global__ void fused_kernel(const float* __restrict__ v,
                             const float* __restrict__ w1,
                             const float* __restrict__ b1,
                             const float* __restrict__ bn_gamma,
                             const float* __restrict__ bn_beta,
                             const float* __restrict__ bn_mean,
                             const float* __restrict__ bn_var,
                             const float* __restrict__ w2,
                             const float* __restrict__ b2,
                             float* __restrict__ out) {
    int b = blockIdx.x;
    int tid = threadIdx.x;

    if (b >= 256) {
        // ---- copy part: v_grouped = v_rel (2M float4 over 2048 blocks) ----
        const float4* __restrict__ v4 = (const float4*)v;
        float4* __restrict__ ov = (float4*)out;
        int i0 = (b - 256) * 1024 + tid;
        float4 r0 = v4[i0];
        float4 r1 = v4[i0 + 256];
        float4 r2 = v4[i0 + 512];
        float4 r3 = v4[i0 + 768];
        ov[i0]       = r0;
        ov[i0 + 256] = r1;
        ov[i0 + 512] = r2;
        ov[i0 + 768] = r3;
        return;
    }

    // ---- dist blocks ----
    __shared__ __align__(1024) float rows[8 * 256];   // 8KB slab
    __shared__ float sa[32], sw0[32], sw1[32], sb_[32];
    __shared__ float sK;
    __shared__ int s_islast;
    if (tid < 32) {
        float scale = bn_gamma[tid] * rsqrtf(bn_var[tid] + EPS_BN);
        float w2o = w2[tid];
        sa[tid]  = w2o * scale;
        sw0[tid] = w1[tid * 2 + 0];
        sw1[tid] = w1[tid * 2 + 1];
        sb_[tid] = b1[tid];
        float kpart = w2o * (bn_beta[tid] - bn_mean[tid] * scale);
        #pragma unroll
        for (int off = 16; off > 0; off >>= 1)
            kpart += __shfl_down_sync(0xffffffffu, kpart, off);
        if (tid == 0) sK = kpart + b2[0];
    }
    __syncthreads();

    int chunk = b & 31;          // 8-row chunk
    int tg    = b >> 5;          // t-group: t = tg*16 .. tg*16+15
    int n0 = chunk * 8;
    int m = tid;
    // x[c][i] = v_rel[0, c, 127, i], layout (1,256,128,256)
    const int base = 127 * 256;
    float x0m = v[base + m];
    float x1m = v[32768 + base + m];

    for (int j = 0; j < 8; j++) {
        int n = n0 + j;
        float d0 = v[base + n] - x0m;           // broadcast load
        float d1 = v[32768 + base + n] - x1m;
        float sp = sK, sn = sK;
        #pragma unroll
        for (int o = 0; o < 32; o++) {
            float lin = sw0[o] * d0 + sw1[o] * d1;
            sp += sa[o] * fmaxf(lin + sb_[o], 0.0f);
            sn += sa[o] * fmaxf(sb_[o] - lin, 0.0f);
        }
        float val = 0.5f * (expf(sp) + expf(sn));
        rows[j * 256 + m] = val;
        if (tg == 0) g_dm[n * 256 + m] = val;
    }
    __syncthreads();

    // TMA S2G broadcast: 16 non-blocking 8KB bulk stores (t = tg*16+j)
    if (tid == 0) {
        asm volatile("fence.proxy.async.shared::cta;" ::: "memory");
        uint32_t sb = smem_u32(rows);
        char* dbase = (char*)out + 33555456L + (long)chunk * 8192;
        #pragma unroll
        for (int j = 0; j < 16; j++) {
            int t = tg * 16 + j;
            s2g(dbase + (long)t * 262144, sb, 8192u);
        }
        asm volatile("cp.async.bulk.commit_group;" ::: "memory");
    }

    if (tg == 0) {
        // rowok for the 8 rows (reads rows[] after the sync above)
        for (int j = 0; j < 8; j++) {
            int n = n0 + j;
            int anyok = __syncthreads_or((m < n) && (rows[j * 256 + m] <= TH));
            if (tid == 0) g_rowok[n] = anyok;
        }
        // ---- done-counter handshake: last tg==0 block computes groups ----
        if (tid == 0) {
            __threadfence();                   // commit g_dm rows + rowok
            int old = atomicAdd(&g_done, 1);
            s_islast = (old == 31);
        }
        __syncthreads();
        if (s_islast) {
            __threadfence();                   // see all rows' writes
            float* __restrict__ out_gi = out + 8388608;
            int rowok = g_rowok[tid];
            bool fast = __syncthreads_and(tid == 0 || rowok);
            if (fast) {
                // every row r>=1 merges into the comp labeled 0 -> all ranks 0
                out_gi[tid] = 0.0f;
            } else {
                // ---- exact fallback: row-parallel replica of lax.scan ----
                __shared__ int comp[256];
                __shared__ int firstidx[256];
                __shared__ int marked[256];
                __shared__ int cstar;
                __shared__ int newcomp;
                comp[tid] = tid;
                __syncthreads();
                for (int r = 1; r < 256; r++) {
                    firstidx[tid] = 0x7fffffff;
                    marked[tid] = 0;
                    if (tid == 0) cstar = -1;
                    __syncthreads();
                    int myc = comp[tid];
                    int rcomp = comp[r];
                    bool okc = (tid < r) && (g_dm[r * 256 + tid] <= TH);
                    if (okc) { atomicMin(&firstidx[myc], tid); marked[myc] = 1; }
                    if (tid == r) marked[myc] = 1;
                    __syncthreads();
                    if (okc && myc != rcomp && firstidx[myc] == tid)
                        atomicMax(&cstar, tid);
                    __syncthreads();
                    int cs = cstar;
                    if (cs >= 0 && tid == cs) newcomp = myc;
                    __syncthreads();
                    if (cs >= 0 && marked[myc]) comp[tid] = newcomp;
                    __syncthreads();
                }
                __shared__ int pres[256];
                pres[tid] = 0;
                __syncthreads();
                pres[comp[tid]] = 1;
                __syncthreads();
                for (int off = 1; off < 256; off <<= 1) {
                    int t = (tid >= off) ? pres[tid - off] : 0;
                    __syncthreads();
                    pres[tid] += t;
                    __syncthreads();
                }
                out_gi[tid] = (float)(pres[comp[tid]] - 1);
            }
            __syncthreads();
            if (tid == 0) g_done = 0;          // reset for next graph replay
        }
    }

    // drain this block's bulk stores before smem is released
    if (tid == 0) {
        asm volatile("cp.async.bulk.wait_group 0;" ::: "memory");
    }
}

extern "C" void kernel_launch(void* const* d_in, const int* in_sizes, int n_in,
                              void* d_out, int out_size) {
    const float* v_rel    = (const float*)d_in[0];
    const float* w1       = (const float*)d_in[1];
    const float* b1       = (const float*)d_in[2];
    const float* bn_gamma = (const float*)d_in[3];
    const float* bn_beta  = (const float*)d_in[4];
    const float* bn_mean  = (const float*)d_in[5];
    const float* bn_var   = (const float*)d_in[6];
    const float* w2       = (const float*)d_in[7];
    const float* b2       = (const float*)d_in[8];
    float* out = (float*)d_out;

    fused_kernel<<<2304, 256>>>(v_rel, w1, b1, bn_gamma, bn_beta, bn_mean,
                                bn_var, w2, b2, out);
}

// round 15
// speedup vs baseline: 1.0869x; 1.0869x over previous
#include <cuda_runtime.h>
#include <cstdint>

#define TH 1.0f
#define EPS_BN 1e-5f

// scratch (no allocations allowed -> device globals)
__device__ float g_dm[256 * 256];
__device__ int   g_rowok[256];
__device__ int   g_done = 0;   // reset by last tg==0 block each run (replay-safe)

__device__ __forceinline__ uint32_t smem_u32(const void* p) {
    uint32_t a;
    asm("{ .reg .u64 t; cvta.to.shared.u64 t, %1; cvt.u32.u64 %0, t; }"
        : "=r"(a) : "l"(p));
    return a;
}
__device__ __forceinline__ void s2g(void* gdst, uint32_t ssrc, uint32_t bytes) {
    asm volatile("cp.async.bulk.global.shared::cta.bulk_group [%0], [%1], %2;"
                 :: "l"(gdst), "r"(ssrc), "r"(bytes) : "memory");
}

// ---------------------------------------------------------------------------
// Single fused kernel, 2304 blocks x 256 threads:
//  b in [0,256)    : dist blocks. chunk=b&63 -> rows n0=chunk*4..+4 (4KB slab
//    in smem, row loop NOT unrolled to keep regs low); tg=b>>6 -> t-copies
//    t = tg*32..+32. One thread issues 32 non-blocking 4KB cp.async.bulk S2G
//    stores into dist_mat_full (TMA path, bypasses L1/LSU).
//    tg==0 blocks also write g_dm rows + rowok and join a 64-count
//    done-counter; the last computes group_indices in-kernel
//    (fast path all-zeros; exact lax.scan replica fallback).
//  b in [256,2304) : float4 slab copy v_rel -> v_grouped on the LSU path
//    (stop_gradient(v - v_soft) + v_soft == v exactly).
// The 67MB copy (L1/LSU) and 33.5MB dist stores (TMA) use separate HW paths.
// ---------------------------------------------------------------------------
__global__ void __launch_bounds__(256)
fused_kernel(const float* __restrict__ v,
             const float* __restrict__ w1,
             const float* __restrict__ b1,
             const float* __restrict__ bn_gamma,
             const float* __restrict__ bn_beta,
             const float* __restrict__ bn_mean,
             const float* __restrict__ bn_var,
             const float* __restrict__ w2,
             const float* __restrict__ b2,
             float* __restrict__ out) {
    int b = blockIdx.x;
    int tid = threadIdx.x;

    if (b >= 256) {
        // ---- copy part: v_grouped = v_rel (2M float4 over 2048 blocks) ----
        const float4* __restrict__ v4 = (const float4*)v;
        float4* __restrict__ ov = (float4*)out;
        int i0 = (b - 256) * 1024 + tid;
        float4 r0 = v4[i0];
        float4 r1 = v4[i0 + 256];
        float4 r2 = v4[i0 + 512];
        float4 r3 = v4[i0 + 768];
        ov[i0]       = r0;
        ov[i0 + 256] = r1;
        ov[i0 + 512] = r2;
        ov[i0 + 768] = r3;
        return;
    }

    // ---- dist blocks ----
    __shared__ __align__(128) float rows[4 * 256];   // 4KB slab
    __shared__ float sa[32], sw0[32], sw1[32], sb_[32];
    __shared__ float sK;
    __shared__ int s_islast;
    if (tid < 32) {
        float scale = bn_gamma[tid] * rsqrtf(bn_var[tid] + EPS_BN);
        float w2o = w2[tid];
        sa[tid]  = w2o * scale;
        sw0[tid] = w1[tid * 2 + 0];
        sw1[tid] = w1[tid * 2 + 1];
        sb_[tid] = b1[tid];
        float kpart = w2o * (bn_beta[tid] - bn_mean[tid] * scale);
        #pragma unroll
        for (int off = 16; off > 0; off >>= 1)
            kpart += __shfl_down_sync(0xffffffffu, kpart, off);
        if (tid == 0) sK = kpart + b2[0];
    }
    __syncthreads();

    int chunk = b & 63;          // rows n0 = chunk*4 .. +4
    int tg    = b >> 6;          // t-copies t = tg*32 .. +32
    int n0 = chunk * 4;
    int m = tid;
    // x[c][i] = v_rel[0, c, 127, i], layout (1,256,128,256)
    const int base = 127 * 256;
    float x0m = v[base + m];
    float x1m = v[32768 + base + m];

    #pragma unroll 1
    for (int j = 0; j < 4; j++) {
        int n = n0 + j;
        float d0 = v[base + n] - x0m;           // broadcast load
        float d1 = v[32768 + base + n] - x1m;
        float sp = sK, sn = sK;
        #pragma unroll
        for (int o = 0; o < 32; o++) {
            float lin = sw0[o] * d0 + sw1[o] * d1;
            sp += sa[o] * fmaxf(lin + sb_[o], 0.0f);
            sn += sa[o] * fmaxf(sb_[o] - lin, 0.0f);
        }
        float val = 0.5f * (expf(sp) + expf(sn));
        rows[j * 256 + m] = val;
        if (tg == 0) g_dm[n * 256 + m] = val;
    }
    __syncthreads();

    // TMA S2G broadcast: 32 non-blocking 4KB bulk stores (t = tg*32+j)
    if (tid == 0) {
        asm volatile("fence.proxy.async.shared::cta;" ::: "memory");
        uint32_t sbuf = smem_u32(rows);
        char* dbase = (char*)out + 33555456L + (long)chunk * 4096;
        #pragma unroll 1
        for (int j = 0; j < 32; j++) {
            int t = tg * 32 + j;
            s2g(dbase + (long)t * 262144, sbuf, 4096u);
        }
        asm volatile("cp.async.bulk.commit_group;" ::: "memory");
    }

    if (tg == 0) {
        // rowok for the 4 rows (reads rows[] after the sync above)
        #pragma unroll 1
        for (int j = 0; j < 4; j++) {
            int n = n0 + j;
            int anyok = __syncthreads_or((m < n) && (rows[j * 256 + m] <= TH));
            if (tid == 0) g_rowok[n] = anyok;
        }
        // ---- done-counter handshake: last tg==0 block computes groups ----
        if (tid == 0) {
            __threadfence();                   // commit g_dm rows + rowok
            int old = atomicAdd(&g_done, 1);
            s_islast = (old == 63);
        }
        __syncthreads();
        if (s_islast) {
            __threadfence();                   // see all rows' writes
            float* __restrict__ out_gi = out + 8388608;
            int rowok = g_rowok[tid];
            bool fast = __syncthreads_and(tid == 0 || rowok);
            if (fast) {
                // every row r>=1 merges into the comp labeled 0 -> all ranks 0
                out_gi[tid] = 0.0f;
            } else {
                // ---- exact fallback: row-parallel replica of lax.scan ----
                __shared__ int comp[256];
                __shared__ int firstidx[256];
                __shared__ int marked[256];
                __shared__ int cstar;
                __shared__ int newcomp;
                comp[tid] = tid;
                __syncthreads();
                for (int r = 1; r < 256; r++) {
                    firstidx[tid] = 0x7fffffff;
                    marked[tid] = 0;
                    if (tid == 0) cstar = -1;
                    __syncthreads();
                    int myc = comp[tid];
                    int rcomp = comp[r];
                    bool okc = (tid < r) && (g_dm[r * 256 + tid] <= TH);
                    if (okc) { atomicMin(&firstidx[myc], tid); marked[myc] = 1; }
                    if (tid == r) marked[myc] = 1;
                    __syncthreads();
                    if (okc && myc != rcomp && firstidx[myc] == tid)
                        atomicMax(&cstar, tid);
                    __syncthreads();
                    int cs = cstar;
                    if (cs >= 0 && tid == cs) newcomp = myc;
                    __syncthreads();
                    if (cs >= 0 && marked[myc]) comp[tid] = newcomp;
                    __syncthreads();
                }
                __shared__ int pres[256];
                pres[tid] = 0;
                __syncthreads();
                pres[comp[tid]] = 1;
                __syncthreads();
                for (int off = 1; off < 256; off <<= 1) {
                    int t = (tid >= off) ? pres[tid - off] : 0;
                    __syncthreads();
                    pres[tid] += t;
                    __syncthreads();
                }
                out_gi[tid] = (float)(pres[comp[tid]] - 1);
            }
            __syncthreads();
            if (tid == 0) g_done = 0;          // reset for next graph replay
        }
    }

    // drain this block's bulk stores before smem is released
    if (tid == 0) {
        asm volatile("cp.async.bulk.wait_group 0;" ::: "memory");
    }
}

extern "C" void kernel_launch(void* const* d_in, const int* in_sizes, int n_in,
                              void* d_out, int out_size) {
    const float* v_rel    = (const float*)d_in[0];
    const float* w1       = (const float*)d_in[1];
    const float* b1       = (const float*)d_in[2];
    const float* bn_gamma = (const float*)d_in[3];
    const float* bn_beta  = (const float*)d_in[4];
    const float* bn_mean  = (const float*)d_in[5];
    const float* bn_var   = (const float*)d_in[6];
    const float* w2       = (const float*)d_in[7];
    const float* b2       = (const float*)d_in[8];
    float* out = (float*)d_out;

    fused_kernel<<<2304, 256>>>(v_rel, w1, b1, bn_gamma, bn_beta, bn_mean,
                                bn_var, w2, b2, out);
}

// round 16
// speedup vs baseline: 1.6294x; 1.4992x over previous
#include <cuda_runtime.h>
#include <cstdint>

#define TH 1.0f
#define EPS_BN 1e-5f

// scratch (no allocations allowed -> device globals)
__device__ float g_dm[256 * 256];
__device__ int   g_rowok[256];
__device__ int   g_done = 0;   // reset by last tg==0 block each run (replay-safe)

__device__ __forceinline__ uint32_t smem_u32(const void* p) {
    uint32_t a;
    asm("{ .reg .u64 t; cvta.to.shared.u64 t, %1; cvt.u32.u64 %0, t; }"
        : "=r"(a) : "l"(p));
    return a;
}
__device__ __forceinline__ void s2g(void* gdst, uint32_t ssrc, uint32_t bytes) {
    asm volatile("cp.async.bulk.global.shared::cta.bulk_group [%0], [%1], %2;"
                 :: "l"(gdst), "r"(ssrc), "r"(bytes) : "memory");
}

// ---------------------------------------------------------------------------
// Single fused kernel, 768 blocks x 1024 threads:
//  b in [0,256)   : dist blocks. chunk=b>>2 -> rows n0=chunk*4..+4; each
//    thread computes EXACTLY ONE MLP value (j=tid>>8, m=tid&255) -> low regs.
//    tg=b&3 -> t-copies t=tg*32..+32; threads 0..31 each issue one 4KB
//    cp.async.bulk S2G into dist_mat_full (TMA path, bypasses L1/LSU).
//    tg==0 blocks also write g_dm rows + rowok, join a 64-count done-counter;
//    the last computes group_indices (fast path all-zeros; exact lax.scan
//    replica fallback, 1024-thread-guarded).
//  b in [256,768) : float4 slab copy v_rel -> v_grouped on the LSU path
//    (stop_gradient(v - v_soft) + v_soft == v exactly).
// ---------------------------------------------------------------------------
__global__ void __launch_bounds__(1024)
fused_kernel(const float* __restrict__ v,
             const float* __restrict__ w1,
             const float* __restrict__ b1,
             const float* __restrict__ bn_gamma,
             const float* __restrict__ bn_beta,
             const float* __restrict__ bn_mean,
             const float* __restrict__ bn_var,
             const float* __restrict__ w2,
             const float* __restrict__ b2,
             float* __restrict__ out) {
    int b = blockIdx.x;
    int tid = threadIdx.x;

    if (b >= 256) {
        // ---- copy part: v_grouped = v_rel (2M float4 over 512 blocks) ----
        const float4* __restrict__ v4 = (const float4*)v;
        float4* __restrict__ ov = (float4*)out;
        int i0 = (b - 256) * 4096 + tid;
        float4 r0 = v4[i0];
        float4 r1 = v4[i0 + 1024];
        float4 r2 = v4[i0 + 2048];
        float4 r3 = v4[i0 + 3072];
        ov[i0]        = r0;
        ov[i0 + 1024] = r1;
        ov[i0 + 2048] = r2;
        ov[i0 + 3072] = r3;
        return;
    }

    // ---- dist blocks ----
    __shared__ __align__(128) float slab[4 * 256];   // 4KB: rows n0..n0+3
    __shared__ float sa[32], sw0[32], sw1[32], sb_[32];
    __shared__ float sK;
    __shared__ int okflags[4];
    __shared__ int s_islast;
    if (tid < 32) {
        float scale = bn_gamma[tid] * rsqrtf(bn_var[tid] + EPS_BN);
        float w2o = w2[tid];
        sa[tid]  = w2o * scale;
        sw0[tid] = w1[tid * 2 + 0];
        sw1[tid] = w1[tid * 2 + 1];
        sb_[tid] = b1[tid];
        float kpart = w2o * (bn_beta[tid] - bn_mean[tid] * scale);
        #pragma unroll
        for (int off = 16; off > 0; off >>= 1)
            kpart += __shfl_down_sync(0xffffffffu, kpart, off);
        if (tid == 0) sK = kpart + b2[0];
    }
    if (tid < 4) okflags[tid] = 0;
    __syncthreads();

    int chunk = b >> 2;          // rows n0 = chunk*4 .. +4
    int tg    = b & 3;           // t-copies t = tg*32 .. +32
    int j = tid >> 8;            // row within slab (0..3)
    int m = tid & 255;           // column
    int n = chunk * 4 + j;
    // x[c][i] = v_rel[0, c, 127, i], layout (1,256,128,256)
    const int base = 127 * 256;
    float d0 = v[base + n] - v[base + m];
    float d1 = v[32768 + base + n] - v[32768 + base + m];

    float sp = sK, sn = sK;
    #pragma unroll
    for (int o = 0; o < 32; o++) {
        float lin = sw0[o] * d0 + sw1[o] * d1;
        sp += sa[o] * fmaxf(lin + sb_[o], 0.0f);
        sn += sa[o] * fmaxf(sb_[o] - lin, 0.0f);
    }
    float val = 0.5f * (expf(sp) + expf(sn));
    slab[j * 256 + m] = val;
    if (tg == 0) {
        g_dm[n * 256 + m] = val;
        if ((m < n) && (val <= TH)) atomicOr(&okflags[j], 1);
    }
    __syncthreads();

    // TMA S2G broadcast: threads 0..31 each issue one 4KB bulk store
    if (tid < 32) {
        asm volatile("fence.proxy.async.shared::cta;" ::: "memory");
        uint32_t sbuf = smem_u32(slab);
        int t = tg * 32 + tid;
        char* dst = (char*)out + 33555456L + (long)t * 262144
                    + (long)chunk * 4096;
        s2g(dst, sbuf, 4096u);
        asm volatile("cp.async.bulk.commit_group;" ::: "memory");
    }

    if (tg == 0) {
        if (tid < 4) g_rowok[chunk * 4 + tid] = okflags[tid];
        // ---- done-counter handshake: last tg==0 block computes groups ----
        if (tid == 0) {
            __threadfence();                   // commit g_dm rows + rowok
            int old = atomicAdd(&g_done, 1);
            s_islast = (old == 63);
        }
        __syncthreads();
        if (s_islast) {
            __threadfence();                   // see all rows' writes
            float* __restrict__ out_gi = out + 8388608;
            bool act = tid < 256;
            int rowok = act ? g_rowok[tid] : 1;
            bool fast = __syncthreads_and(tid == 0 || rowok != 0);
            if (fast) {
                // every row r>=1 merges into comp labeled 0 -> all ranks 0
                if (act) out_gi[tid] = 0.0f;
            } else {
                // ---- exact fallback: row-parallel replica of lax.scan ----
                __shared__ int comp[256];
                __shared__ int firstidx[256];
                __shared__ int marked[256];
                __shared__ int cstar;
                __shared__ int newcomp;
                if (act) comp[tid] = tid;
                __syncthreads();
                for (int r = 1; r < 256; r++) {
                    if (act) { firstidx[tid] = 0x7fffffff; marked[tid] = 0; }
                    if (tid == 0) cstar = -1;
                    __syncthreads();
                    int myc = 0, rcomp = 0;
                    bool okc = false;
                    if (act) {
                        myc = comp[tid];
                        rcomp = comp[r];
                        okc = (tid < r) && (g_dm[r * 256 + tid] <= TH);
                        if (okc) { atomicMin(&firstidx[myc], tid); marked[myc] = 1; }
                        if (tid == r) marked[myc] = 1;
                    }
                    __syncthreads();
                    if (act && okc && myc != rcomp && firstidx[myc] == tid)
                        atomicMax(&cstar, tid);
                    __syncthreads();
                    int cs = cstar;
                    if (cs >= 0 && tid == cs) newcomp = myc;
                    __syncthreads();
                    if (act && cs >= 0 && marked[myc]) comp[tid] = newcomp;
                    __syncthreads();
                }
                __shared__ int pres[256];
                if (act) pres[tid] = 0;
                __syncthreads();
                if (act) pres[comp[tid]] = 1;
                __syncthreads();
                for (int off = 1; off < 256; off <<= 1) {
                    int t = (act && tid >= off) ? pres[tid - off] : 0;
                    __syncthreads();
                    if (act) pres[tid] += t;
                    __syncthreads();
                }
                if (act) out_gi[tid] = (float)(pres[comp[tid]] - 1);
            }
            __syncthreads();
            if (tid == 0) g_done = 0;          // reset for next graph replay
        }
    }

    // drain this thread's bulk store before smem is released
    if (tid < 32) {
        asm volatile("cp.async.bulk.wait_group 0;" ::: "memory");
    }
}

extern "C" void kernel_launch(void* const* d_in, const int* in_sizes, int n_in,
                              void* d_out, int out_size) {
    const float* v_rel    = (const float*)d_in[0];
    const float* w1       = (const float*)d_in[1];
    const float* b1       = (const float*)d_in[2];
    const float* bn_gamma = (const float*)d_in[3];
    const float* bn_beta  = (const float*)d_in[4];
    const float* bn_mean  = (const float*)d_in[5];
    const float* bn_var   = (const float*)d_in[6];
    const float* w2       = (const float*)d_in[7];
    const float* b2       = (const float*)d_in[8];
    float* out = (float*)d_out;

    fused_kernel<<<768, 1024>>>(v_rel, w1, b1, bn_gamma, bn_beta, bn_mean,
                                bn_var, w2, b2, out);
}